// round 11
// baseline (speedup 1.0000x reference)
#include <cuda_runtime.h>
#include <cstdint>

#define NROI      256
#define NCH       256
#define NPTS      7
#define HP        8
#define H0F       200
#define W0F       336
#define IMG_W     1344.0f
#define IMG_H     800.0f

// ---------------------------------------------------------------------------
// Fused zero+gather pooler with PAIRED-TAP vector gathers.
//
// L1-wavefront analysis showed the 4 scalar gather LDGs per (warp,channel)
// are the wall (~13 wavefronts each warp-channel). Since x1 = x0+1, one
// ALIGNED float4 window per feature row covers both x-taps for almost all
// lanes: 2 LDG.128 + 2 rarely-active predicated scalar LDGs per channel
// (~8-9 wavefronts). Extraction is free: per-thread PERMUTED WEIGHT float4s
// (w00/w10 scattered into window slots, OOB masks folded) turn the sample
// into a 10-term FMA dot product. xbase clamped to W-4 keeps the window
// inside the row (no OOB reads). f3 (W=42, rows not 16B-aligned) uses the
// scalar fallback.
//
// Grid (8, NROI), R10 structure: each block zeros its mismatched-output
// region (store burst) then gathers its matched region.
// ---------------------------------------------------------------------------

template <int CCH, int YROWS, int WP>
__device__ __forceinline__ void zero_region(
    float* __restrict__ outp, int n, int c0, int yblk) {
    constexpr int F4_PER_CH = YROWS * WP / 4;
    const float4 z = make_float4(0.f, 0.f, 0.f, 0.f);
#pragma unroll
    for (int t = 0; t < CCH * F4_PER_CH / 256; t++) {
        int idx = t * 256 + threadIdx.x;
        int c   = idx / F4_PER_CH;
        int off = idx % F4_PER_CH;
        float4* zp = (float4*)(outp +
            (((size_t)n * NCH + c0 + c) * HP + yblk * YROWS) * WP) + off;
        __stcs(zp, z);
    }
}

template <int WP, int YROWS, int CCH>
__device__ __forceinline__ void gather_region(
    int c0, int yblk, int n,
    const float* __restrict__ f0, const float* __restrict__ f1,
    const float* __restrict__ f2, const float* __restrict__ f3,
    float* __restrict__ outp, const float* __restrict__ pp,
    int s_lvl, int s_img) {

    const int x = threadIdx.x % WP;
    const int y = yblk * YROWS + threadIdx.x / WP;

    int H, W;
    const float* feat;
    switch (s_lvl) {
        case 0:  H = H0F;     W = W0F;     feat = f0; break;
        case 1:  H = H0F / 2; W = W0F / 2; feat = f1; break;
        case 2:  H = H0F / 4; W = W0F / 4; feat = f2; break;
        default: H = H0F / 8; W = W0F / 8; feat = f3; break;
    }
    const size_t HW = (size_t)H * W;
    const float* p = feat + ((size_t)s_img * NCH + c0) * HW;
    float* op = outp + (((size_t)n * NCH + c0) * HP + y) * WP + x;

    const float v    = (y + 0.5f) * (1.0f / HP);
    const float invW = 1.0f / IMG_W, invH = 1.0f / IMG_H;

    float u = (x + 0.5f) * ((float)(NPTS - 1) / (float)WP);
    int i0 = (int)floorf(u);
    i0 = max(0, min(i0, NPTS - 2));
    float f = u - (float)i0;
    int j0 = 13 - i0, j1 = 12 - i0;

    float tx = (__ldg(pp + 2*i0)     * (1.0f - f) + __ldg(pp + 2*(i0+1))     * f) * invW;
    float ty = (__ldg(pp + 2*i0 + 1) * (1.0f - f) + __ldg(pp + 2*(i0+1) + 1) * f) * invH;
    float bx = (__ldg(pp + 2*j0)     * (1.0f - f) + __ldg(pp + 2*j1)         * f) * invW;
    float by = (__ldg(pp + 2*j0 + 1) * (1.0f - f) + __ldg(pp + 2*j1 + 1)     * f) * invH;

    float gx = tx * (1.0f - v) + bx * v;
    float gy = ty * (1.0f - v) + by * v;

    float xf = gx * (float)W - 0.5f;
    float yf = gy * (float)H - 0.5f;
    float x0f = floorf(xf), y0f = floorf(yf);
    float wx = xf - x0f, wy = yf - y0f;
    int x0 = (int)x0f, y0i = (int)y0f;
    int x1 = x0 + 1,   y1 = y0i + 1;

    int x0c = min(max(x0, 0), W - 1), x1c = min(max(x1, 0), W - 1);
    int y0c = min(max(y0i, 0), H - 1), y1c = min(max(y1, 0), H - 1);
    float m00 = ((x0 >= 0) & (x0 < W) & (y0i >= 0) & (y0i < H)) ? 1.0f : 0.0f;
    float m10 = ((x1 >= 0) & (x1 < W) & (y0i >= 0) & (y0i < H)) ? 1.0f : 0.0f;
    float m01 = ((x0 >= 0) & (x0 < W) & (y1 >= 0) & (y1 < H)) ? 1.0f : 0.0f;
    float m11 = ((x1 >= 0) & (x1 < W) & (y1 >= 0) & (y1 < H)) ? 1.0f : 0.0f;

    const float w00 = m00 * (1.0f - wx) * (1.0f - wy);
    const float w10 = m10 * wx          * (1.0f - wy);
    const float w01 = m01 * (1.0f - wx) * wy;
    const float w11 = m11 * wx          * wy;

    constexpr size_t OST = (size_t)HP * WP;

    if (s_lvl < 3) {
        // ---- vector path: paired-tap aligned float4 gathers ----
        // (W = 336 / 168 / 84 -> rows 16B-aligned, W % 4 == 0)
        const int xbase = min(x0c & ~3, W - 4);   // window stays inside row
        const int e0 = x0c - xbase;               // 0..3
        const int e1 = x1c - xbase;               // 0..4
        const bool cross = (e1 > 3);              // x1 outside window

        // Permuted weight vectors: slot k gets w00 (if e0==k) + w10 (if e1==k)
        float4 Wr0, Wr1;
        Wr0.x = ((e0 == 0) ? w00 : 0.f) + ((!cross && e1 == 0) ? w10 : 0.f);
        Wr0.y = ((e0 == 1) ? w00 : 0.f) + ((!cross && e1 == 1) ? w10 : 0.f);
        Wr0.z = ((e0 == 2) ? w00 : 0.f) + ((!cross && e1 == 2) ? w10 : 0.f);
        Wr0.w = ((e0 == 3) ? w00 : 0.f) + ((!cross && e1 == 3) ? w10 : 0.f);
        Wr1.x = ((e0 == 0) ? w01 : 0.f) + ((!cross && e1 == 0) ? w11 : 0.f);
        Wr1.y = ((e0 == 1) ? w01 : 0.f) + ((!cross && e1 == 1) ? w11 : 0.f);
        Wr1.z = ((e0 == 2) ? w01 : 0.f) + ((!cross && e1 == 2) ? w11 : 0.f);
        Wr1.w = ((e0 == 3) ? w01 : 0.f) + ((!cross && e1 == 3) ? w11 : 0.f);
        const float wc0 = cross ? w10 : 0.f;
        const float wc1 = cross ? w11 : 0.f;

        const int a0  = y0c * W + xbase;
        const int a1  = y1c * W + xbase;
        const int oc0 = y0c * W + x1c;
        const int oc1 = y1c * W + x1c;

#pragma unroll 4
        for (int c = 0; c < CCH; c++) {
            const float4 ra = __ldg((const float4*)(p + a0));
            const float4 rb = __ldg((const float4*)(p + a1));
            float vc0 = cross ? __ldg(p + oc0) : 0.f;
            float vc1 = cross ? __ldg(p + oc1) : 0.f;
            float r = ra.x * Wr0.x + ra.y * Wr0.y + ra.z * Wr0.z + ra.w * Wr0.w
                    + rb.x * Wr1.x + rb.y * Wr1.y + rb.z * Wr1.z + rb.w * Wr1.w
                    + vc0 * wc0 + vc1 * wc1;
            __stcs(op + (size_t)c * OST, r);
            p += HW;
        }
    } else {
        // ---- scalar fallback (f3: W=42, rows not 16B-aligned) ----
        const int o00 = y0c * W + x0c;
        const int o10 = y0c * W + x1c;
        const int o01 = y1c * W + x0c;
        const int o11 = y1c * W + x1c;
#pragma unroll 8
        for (int c = 0; c < CCH; c++) {
            float v00 = __ldg(p + o00);
            float v10 = __ldg(p + o10);
            float v01 = __ldg(p + o01);
            float v11 = __ldg(p + o11);
            float r = v00 * w00 + v10 * w10 + v01 * w01 + v11 * w11;
            __stcs(op + (size_t)c * OST, r);
            p += HW;
        }
    }
}

__global__ void __launch_bounds__(256, 4)
fused_pool_kernel(const float* __restrict__ f0, const float* __restrict__ f1,
                  const float* __restrict__ f2, const float* __restrict__ f3,
                  const float* __restrict__ polys, const int* __restrict__ img_ids,
                  const int* __restrict__ lens, float* __restrict__ out) {
    const int n  = blockIdx.y;
    const int bx = blockIdx.x;
    const float* pp = polys + (size_t)n * (2 * NPTS * 2);

    // --- per-thread uniform meta (broadcast __ldg; no smem, no barriers) ---
    float minx = __ldg(pp + 0), maxx = minx;
    float miny = __ldg(pp + 1), maxy = miny;
#pragma unroll
    for (int i = 1; i < 2 * NPTS; i++) {
        float px = __ldg(pp + 2 * i), py = __ldg(pp + 2 * i + 1);
        minx = fminf(minx, px); maxx = fmaxf(maxx, px);
        miny = fminf(miny, py); maxy = fmaxf(maxy, py);
    }
    float s  = sqrtf((maxx - minx) * (maxy - miny));
    float vv = 4.0f + log2f(s / 224.0f + 1e-6f);
    float fl = fminf(fmaxf(floorf(vv), 2.0f), 5.0f);
    const int s_lvl = (int)fl - 2;
    const int s_pid = (__ldg(lens + n) > 8) ? 1 : 0;
    const int s_img = __ldg(img_ids + n);

    float* out1 = out + (size_t)NROI * NCH * HP * 32;

    // This block's portions:
    //   out0: channels [bx*32, +32), yblk 0 (all 8 rows), WP=32
    //   out1: channels [(bx>>1)*64, +64), yblk = bx&1 (4 rows), WP=64
    const int c0_o0 = bx * 32;
    const int c0_o1 = (bx >> 1) * 64;
    const int yb_o1 = bx & 1;

    if (s_pid == 0) {
        zero_region<64, 4, 64>(out1, n, c0_o1, yb_o1);
        gather_region<32, 8, 32>(c0_o0, 0, n, f0, f1, f2, f3,
                                 out, pp, s_lvl, s_img);
    } else {
        zero_region<32, 8, 32>(out, n, c0_o0, 0);
        gather_region<64, 4, 64>(c0_o1, yb_o1, n, f0, f1, f2, f3,
                                 out1, pp, s_lvl, s_img);
    }
}

extern "C" void kernel_launch(void* const* d_in, const int* in_sizes, int n_in,
                              void* d_out, int out_size) {
    const float* f0     = (const float*)d_in[0];
    const float* f1     = (const float*)d_in[1];
    const float* f2     = (const float*)d_in[2];
    const float* f3     = (const float*)d_in[3];
    const float* polys  = (const float*)d_in[4];
    const int*   imgids = (const int*)  d_in[5];
    const int*   lens   = (const int*)  d_in[6];
    float* out = (float*)d_out;

    const int N = in_sizes[4] / (2 * NPTS * 2);   // 256

    dim3 grid(8, N);                              // 2048 uniform blocks
    fused_pool_kernel<<<grid, 256>>>(f0, f1, f2, f3, polys, imgids, lens, out);
}

// round 12
// speedup vs baseline: 1.8331x; 1.8331x over previous
#include <cuda_runtime.h>
#include <cstdint>

#define NROI      256
#define NCH       256
#define NPTS      7
#define HP        8
#define H0F       200
#define W0F       336
#define IMG_W     1344.0f
#define IMG_H     800.0f

// ---------------------------------------------------------------------------
// Fused zero+gather pooler (R10 — measured optimum). Grid (8, NROI): each
// block owns, for its ROI,
//   - out0 chunk:  channels [bx*32, bx*32+32), all 8 y, 32 x
//   - out1 slice:  channels [(bx>>1)*64, +64), y-half (bx&1), 64 x
// The block ZEROS the output its ROI does not match (pure __stcs stream,
// issued first: primes DRAM, no dependencies), then GATHERS the matched
// output with the proven lane-contiguous loop (4 scalar LDG + 1 STG per
// channel, unroll 8, 48-reg budget, occupancy 5).
//
// Validated model: kernel time == L1tex wavefront budget (~10.4M wf). Scalar
// lane-contiguous taps are wavefront-minimal; vector taps (R11) violate the
// 128B/wf byte floor and regress; wider load windows (R8) spill and regress.
// ---------------------------------------------------------------------------

template <int CCH, int YROWS, int WP>
__device__ __forceinline__ void zero_region(
    float* __restrict__ outp, int n, int c0, int yblk) {
    constexpr int F4_PER_CH = YROWS * WP / 4;
    const float4 z = make_float4(0.f, 0.f, 0.f, 0.f);
#pragma unroll
    for (int t = 0; t < CCH * F4_PER_CH / 256; t++) {
        int idx = t * 256 + threadIdx.x;
        int c   = idx / F4_PER_CH;
        int off = idx % F4_PER_CH;
        float4* zp = (float4*)(outp +
            (((size_t)n * NCH + c0 + c) * HP + yblk * YROWS) * WP) + off;
        __stcs(zp, z);
    }
}

template <int WP, int YROWS, int CCH>
__device__ __forceinline__ void gather_region(
    int c0, int yblk, int n,
    const float* __restrict__ f0, const float* __restrict__ f1,
    const float* __restrict__ f2, const float* __restrict__ f3,
    float* __restrict__ outp, const float* __restrict__ pp,
    int s_lvl, int s_img) {

    const int x = threadIdx.x % WP;
    const int y = yblk * YROWS + threadIdx.x / WP;

    int H, W;
    const float* feat;
    switch (s_lvl) {
        case 0:  H = H0F;     W = W0F;     feat = f0; break;
        case 1:  H = H0F / 2; W = W0F / 2; feat = f1; break;
        case 2:  H = H0F / 4; W = W0F / 4; feat = f2; break;
        default: H = H0F / 8; W = W0F / 8; feat = f3; break;
    }
    const size_t HW = (size_t)H * W;
    const float* p = feat + ((size_t)s_img * NCH + c0) * HW;
    float* op = outp + (((size_t)n * NCH + c0) * HP + y) * WP + x;

    const float v    = (y + 0.5f) * (1.0f / HP);
    const float invW = 1.0f / IMG_W, invH = 1.0f / IMG_H;

    float u = (x + 0.5f) * ((float)(NPTS - 1) / (float)WP);
    int i0 = (int)floorf(u);
    i0 = max(0, min(i0, NPTS - 2));
    float f = u - (float)i0;
    int j0 = 13 - i0, j1 = 12 - i0;

    float tx = (__ldg(pp + 2*i0)     * (1.0f - f) + __ldg(pp + 2*(i0+1))     * f) * invW;
    float ty = (__ldg(pp + 2*i0 + 1) * (1.0f - f) + __ldg(pp + 2*(i0+1) + 1) * f) * invH;
    float bx = (__ldg(pp + 2*j0)     * (1.0f - f) + __ldg(pp + 2*j1)         * f) * invW;
    float by = (__ldg(pp + 2*j0 + 1) * (1.0f - f) + __ldg(pp + 2*j1 + 1)     * f) * invH;

    float gx = tx * (1.0f - v) + bx * v;
    float gy = ty * (1.0f - v) + by * v;

    float xf = gx * (float)W - 0.5f;
    float yf = gy * (float)H - 0.5f;
    float x0f = floorf(xf), y0f = floorf(yf);
    float wx = xf - x0f, wy = yf - y0f;
    int x0 = (int)x0f, y0i = (int)y0f;
    int x1 = x0 + 1,   y1 = y0i + 1;

    int x0c = min(max(x0, 0), W - 1), x1c = min(max(x1, 0), W - 1);
    int y0c = min(max(y0i, 0), H - 1), y1c = min(max(y1, 0), H - 1);
    float m00 = ((x0 >= 0) & (x0 < W) & (y0i >= 0) & (y0i < H)) ? 1.0f : 0.0f;
    float m10 = ((x1 >= 0) & (x1 < W) & (y0i >= 0) & (y0i < H)) ? 1.0f : 0.0f;
    float m01 = ((x0 >= 0) & (x0 < W) & (y1 >= 0) & (y1 < H)) ? 1.0f : 0.0f;
    float m11 = ((x1 >= 0) & (x1 < W) & (y1 >= 0) & (y1 < H)) ? 1.0f : 0.0f;

    const float w00 = m00 * (1.0f - wx) * (1.0f - wy);
    const float w10 = m10 * wx          * (1.0f - wy);
    const float w01 = m01 * (1.0f - wx) * wy;
    const float w11 = m11 * wx          * wy;

    const int o00 = y0c * W + x0c;
    const int o10 = y0c * W + x1c;
    const int o01 = y1c * W + x0c;
    const int o11 = y1c * W + x1c;

    constexpr size_t OST = (size_t)HP * WP;

#pragma unroll 8
    for (int c = 0; c < CCH; c++) {
        float v00 = __ldg(p + o00);
        float v10 = __ldg(p + o10);
        float v01 = __ldg(p + o01);
        float v11 = __ldg(p + o11);
        float r = v00 * w00 + v10 * w10 + v01 * w01 + v11 * w11;
        __stcs(op + (size_t)c * OST, r);
        p += HW;
    }
}

__global__ void __launch_bounds__(256, 5)
fused_pool_kernel(const float* __restrict__ f0, const float* __restrict__ f1,
                  const float* __restrict__ f2, const float* __restrict__ f3,
                  const float* __restrict__ polys, const int* __restrict__ img_ids,
                  const int* __restrict__ lens, float* __restrict__ out) {
    const int n  = blockIdx.y;
    const int bx = blockIdx.x;
    const float* pp = polys + (size_t)n * (2 * NPTS * 2);

    // --- per-thread uniform meta (broadcast __ldg; no smem, no barriers) ---
    float minx = __ldg(pp + 0), maxx = minx;
    float miny = __ldg(pp + 1), maxy = miny;
#pragma unroll
    for (int i = 1; i < 2 * NPTS; i++) {
        float px = __ldg(pp + 2 * i), py = __ldg(pp + 2 * i + 1);
        minx = fminf(minx, px); maxx = fmaxf(maxx, px);
        miny = fminf(miny, py); maxy = fmaxf(maxy, py);
    }
    float s  = sqrtf((maxx - minx) * (maxy - miny));
    float vv = 4.0f + log2f(s / 224.0f + 1e-6f);
    float fl = fminf(fmaxf(floorf(vv), 2.0f), 5.0f);
    const int s_lvl = (int)fl - 2;
    const int s_pid = (__ldg(lens + n) > 8) ? 1 : 0;
    const int s_img = __ldg(img_ids + n);

    float* out1 = out + (size_t)NROI * NCH * HP * 32;

    // This block's portions:
    //   out0: channels [bx*32, +32), yblk 0 (all 8 rows), WP=32
    //   out1: channels [(bx>>1)*64, +64), yblk = bx&1 (4 rows), WP=64
    const int c0_o0 = bx * 32;
    const int c0_o1 = (bx >> 1) * 64;
    const int yb_o1 = bx & 1;

    if (s_pid == 0) {
        // zero mismatched out1 slice first (store burst), then gather out0
        zero_region<64, 4, 64>(out1, n, c0_o1, yb_o1);
        gather_region<32, 8, 32>(c0_o0, 0, n, f0, f1, f2, f3,
                                 out, pp, s_lvl, s_img);
    } else {
        // zero mismatched out0 chunk first, then gather out1 slice
        zero_region<32, 8, 32>(out, n, c0_o0, 0);
        gather_region<64, 4, 64>(c0_o1, yb_o1, n, f0, f1, f2, f3,
                                 out1, pp, s_lvl, s_img);
    }
}

extern "C" void kernel_launch(void* const* d_in, const int* in_sizes, int n_in,
                              void* d_out, int out_size) {
    const float* f0     = (const float*)d_in[0];
    const float* f1     = (const float*)d_in[1];
    const float* f2     = (const float*)d_in[2];
    const float* f3     = (const float*)d_in[3];
    const float* polys  = (const float*)d_in[4];
    const int*   imgids = (const int*)  d_in[5];
    const int*   lens   = (const int*)  d_in[6];
    float* out = (float*)d_out;

    const int N = in_sizes[4] / (2 * NPTS * 2);   // 256

    dim3 grid(8, N);                              // 2048 uniform blocks
    fused_pool_kernel<<<grid, 256>>>(f0, f1, f2, f3, polys, imgids, lens, out);
}

// round 13
// speedup vs baseline: 2.1124x; 1.1524x over previous
#include <cuda_runtime.h>
#include <cstdint>

#define NROI      256
#define NCH       256
#define NPTS      7
#define HP        8
#define H0F       200
#define W0F       336
#define IMG_W     1344.0f
#define IMG_H     800.0f

// ---------------------------------------------------------------------------
// Fused zero+gather pooler with PHASE-STAGGERED block schedule.
//
// R10 structure (measured optimum): grid (8, NROI); each block owns its
// ROI's out0 chunk (32 ch x 8 y x 32 x) and out1 slice (64 ch x 4 y x 64 x),
// zeros the mismatched output and gathers the matched one with the proven
// lane-contiguous loop (4 scalar LDG + 1 STG per channel, unroll 8, 48 regs).
//
// NEW: the zero/gather ORDER alternates by (bx ^ n) parity, so at any
// instant roughly half the resident blocks are in their store burst and half
// in their gather phase -> DRAM-write and L1tex/LSU demand interleave
// chip-wide instead of surging in lockstep at wave starts.
// ---------------------------------------------------------------------------

template <int CCH, int YROWS, int WP>
__device__ __forceinline__ void zero_region(
    float* __restrict__ outp, int n, int c0, int yblk) {
    constexpr int F4_PER_CH = YROWS * WP / 4;
    const float4 z = make_float4(0.f, 0.f, 0.f, 0.f);
#pragma unroll
    for (int t = 0; t < CCH * F4_PER_CH / 256; t++) {
        int idx = t * 256 + threadIdx.x;
        int c   = idx / F4_PER_CH;
        int off = idx % F4_PER_CH;
        float4* zp = (float4*)(outp +
            (((size_t)n * NCH + c0 + c) * HP + yblk * YROWS) * WP) + off;
        __stcs(zp, z);
    }
}

template <int WP, int YROWS, int CCH>
__device__ __forceinline__ void gather_region(
    int c0, int yblk, int n,
    const float* __restrict__ f0, const float* __restrict__ f1,
    const float* __restrict__ f2, const float* __restrict__ f3,
    float* __restrict__ outp, const float* __restrict__ pp,
    int s_lvl, int s_img) {

    const int x = threadIdx.x % WP;
    const int y = yblk * YROWS + threadIdx.x / WP;

    int H, W;
    const float* feat;
    switch (s_lvl) {
        case 0:  H = H0F;     W = W0F;     feat = f0; break;
        case 1:  H = H0F / 2; W = W0F / 2; feat = f1; break;
        case 2:  H = H0F / 4; W = W0F / 4; feat = f2; break;
        default: H = H0F / 8; W = W0F / 8; feat = f3; break;
    }
    const size_t HW = (size_t)H * W;
    const float* p = feat + ((size_t)s_img * NCH + c0) * HW;
    float* op = outp + (((size_t)n * NCH + c0) * HP + y) * WP + x;

    const float v    = (y + 0.5f) * (1.0f / HP);
    const float invW = 1.0f / IMG_W, invH = 1.0f / IMG_H;

    float u = (x + 0.5f) * ((float)(NPTS - 1) / (float)WP);
    int i0 = (int)floorf(u);
    i0 = max(0, min(i0, NPTS - 2));
    float f = u - (float)i0;
    int j0 = 13 - i0, j1 = 12 - i0;

    float tx = (__ldg(pp + 2*i0)     * (1.0f - f) + __ldg(pp + 2*(i0+1))     * f) * invW;
    float ty = (__ldg(pp + 2*i0 + 1) * (1.0f - f) + __ldg(pp + 2*(i0+1) + 1) * f) * invH;
    float bx = (__ldg(pp + 2*j0)     * (1.0f - f) + __ldg(pp + 2*j1)         * f) * invW;
    float by = (__ldg(pp + 2*j0 + 1) * (1.0f - f) + __ldg(pp + 2*j1 + 1)     * f) * invH;

    float gx = tx * (1.0f - v) + bx * v;
    float gy = ty * (1.0f - v) + by * v;

    float xf = gx * (float)W - 0.5f;
    float yf = gy * (float)H - 0.5f;
    float x0f = floorf(xf), y0f = floorf(yf);
    float wx = xf - x0f, wy = yf - y0f;
    int x0 = (int)x0f, y0i = (int)y0f;
    int x1 = x0 + 1,   y1 = y0i + 1;

    int x0c = min(max(x0, 0), W - 1), x1c = min(max(x1, 0), W - 1);
    int y0c = min(max(y0i, 0), H - 1), y1c = min(max(y1, 0), H - 1);
    float m00 = ((x0 >= 0) & (x0 < W) & (y0i >= 0) & (y0i < H)) ? 1.0f : 0.0f;
    float m10 = ((x1 >= 0) & (x1 < W) & (y0i >= 0) & (y0i < H)) ? 1.0f : 0.0f;
    float m01 = ((x0 >= 0) & (x0 < W) & (y1 >= 0) & (y1 < H)) ? 1.0f : 0.0f;
    float m11 = ((x1 >= 0) & (x1 < W) & (y1 >= 0) & (y1 < H)) ? 1.0f : 0.0f;

    const float w00 = m00 * (1.0f - wx) * (1.0f - wy);
    const float w10 = m10 * wx          * (1.0f - wy);
    const float w01 = m01 * (1.0f - wx) * wy;
    const float w11 = m11 * wx          * wy;

    const int o00 = y0c * W + x0c;
    const int o10 = y0c * W + x1c;
    const int o01 = y1c * W + x0c;
    const int o11 = y1c * W + x1c;

    constexpr size_t OST = (size_t)HP * WP;

#pragma unroll 8
    for (int c = 0; c < CCH; c++) {
        float v00 = __ldg(p + o00);
        float v10 = __ldg(p + o10);
        float v01 = __ldg(p + o01);
        float v11 = __ldg(p + o11);
        float r = v00 * w00 + v10 * w10 + v01 * w01 + v11 * w11;
        __stcs(op + (size_t)c * OST, r);
        p += HW;
    }
}

__global__ void __launch_bounds__(256, 5)
fused_pool_kernel(const float* __restrict__ f0, const float* __restrict__ f1,
                  const float* __restrict__ f2, const float* __restrict__ f3,
                  const float* __restrict__ polys, const int* __restrict__ img_ids,
                  const int* __restrict__ lens, float* __restrict__ out) {
    const int n  = blockIdx.y;
    const int bx = blockIdx.x;
    const float* pp = polys + (size_t)n * (2 * NPTS * 2);

    // --- per-thread uniform meta (broadcast __ldg; no smem, no barriers) ---
    float minx = __ldg(pp + 0), maxx = minx;
    float miny = __ldg(pp + 1), maxy = miny;
#pragma unroll
    for (int i = 1; i < 2 * NPTS; i++) {
        float px = __ldg(pp + 2 * i), py = __ldg(pp + 2 * i + 1);
        minx = fminf(minx, px); maxx = fmaxf(maxx, px);
        miny = fminf(miny, py); maxy = fmaxf(maxy, py);
    }
    float s  = sqrtf((maxx - minx) * (maxy - miny));
    float vv = 4.0f + log2f(s / 224.0f + 1e-6f);
    float fl = fminf(fmaxf(floorf(vv), 2.0f), 5.0f);
    const int s_lvl = (int)fl - 2;
    const int s_pid = (__ldg(lens + n) > 8) ? 1 : 0;
    const int s_img = __ldg(img_ids + n);

    float* out1 = out + (size_t)NROI * NCH * HP * 32;

    // This block's portions:
    //   out0: channels [bx*32, +32), yblk 0 (all 8 rows), WP=32
    //   out1: channels [(bx>>1)*64, +64), yblk = bx&1 (4 rows), WP=64
    const int c0_o0 = bx * 32;
    const int c0_o1 = (bx >> 1) * 64;
    const int yb_o1 = bx & 1;

    // Phase stagger: alternate zero/gather order by block parity so store
    // bursts and gather phases interleave chip-wide.
    const bool gather_first = ((bx ^ n) & 1) != 0;

    if (s_pid == 0) {
        if (gather_first) {
            gather_region<32, 8, 32>(c0_o0, 0, n, f0, f1, f2, f3,
                                     out, pp, s_lvl, s_img);
            zero_region<64, 4, 64>(out1, n, c0_o1, yb_o1);
        } else {
            zero_region<64, 4, 64>(out1, n, c0_o1, yb_o1);
            gather_region<32, 8, 32>(c0_o0, 0, n, f0, f1, f2, f3,
                                     out, pp, s_lvl, s_img);
        }
    } else {
        if (gather_first) {
            gather_region<64, 4, 64>(c0_o1, yb_o1, n, f0, f1, f2, f3,
                                     out1, pp, s_lvl, s_img);
            zero_region<32, 8, 32>(out, n, c0_o0, 0);
        } else {
            zero_region<32, 8, 32>(out, n, c0_o0, 0);
            gather_region<64, 4, 64>(c0_o1, yb_o1, n, f0, f1, f2, f3,
                                     out1, pp, s_lvl, s_img);
        }
    }
}

extern "C" void kernel_launch(void* const* d_in, const int* in_sizes, int n_in,
                              void* d_out, int out_size) {
    const float* f0     = (const float*)d_in[0];
    const float* f1     = (const float*)d_in[1];
    const float* f2     = (const float*)d_in[2];
    const float* f3     = (const float*)d_in[3];
    const float* polys  = (const float*)d_in[4];
    const int*   imgids = (const int*)  d_in[5];
    const int*   lens   = (const int*)  d_in[6];
    float* out = (float*)d_out;

    const int N = in_sizes[4] / (2 * NPTS * 2);   // 256

    dim3 grid(8, N);                              // 2048 uniform blocks
    fused_pool_kernel<<<grid, 256>>>(f0, f1, f2, f3, polys, imgids, lens, out);
}